// round 6
// baseline (speedup 1.0000x reference)
#include <cuda_runtime.h>
#include <cuda_fp16.h>
#include <cstdint>

#define NN 8192
#define DD 128
#define PP 4
#define KO 512            // original concat feature dim
#define KE 1536           // split-3 extended K
#define EPS 0.3f
#define EMAX (1 << 19)
#define OUT_DESCALE 0.00390625f   // 2^-8 (exact)

// Scratch (allocation banned -> __device__ globals)
__device__ __half d_A[(size_t)NN * KE];   // 24 MB: [hi*2^4 | hi*2^-2 | lo*2^10]
__device__ __half d_B[(size_t)NN * KE];   // 24 MB: [hi*2^4 | lo*2^10 | hi*2^-2]
__device__ float  d_og[(size_t)NN * NN];  // only edge positions ever touched
__device__ float  d_val[EMAX];

// ---------------------------------------------------------------------------
__device__ __forceinline__ uint32_t smem_u32(const void* p) {
    uint32_t a;
    asm("{ .reg .u64 t; cvta.to.shared.u64 t, %1; cvt.u32.u64 %0, t; }" : "=r"(a) : "l"(p));
    return a;
}
__device__ __forceinline__ void ldsm_x4(uint32_t* r, uint32_t addr) {
    asm volatile("ldmatrix.sync.aligned.m8n8.x4.shared.b16 {%0,%1,%2,%3}, [%4];"
                 : "=r"(r[0]), "=r"(r[1]), "=r"(r[2]), "=r"(r[3]) : "r"(addr));
}
// chained accumulate: c = a*b + c  (tensor-unit add)
__device__ __forceinline__ void mma_acc(float* c, const uint32_t* a,
                                        uint32_t b0, uint32_t b1) {
    asm volatile(
        "mma.sync.aligned.m16n8k16.row.col.f32.f16.f16.f32 "
        "{%0,%1,%2,%3},{%4,%5,%6,%7},{%8,%9},{%0,%1,%2,%3};"
        : "+f"(c[0]), "+f"(c[1]), "+f"(c[2]), "+f"(c[3])
        : "r"(a[0]), "r"(a[1]), "r"(a[2]), "r"(a[3]), "r"(b0), "r"(b1));
}
// fresh-segment form: c = a*b + 0  (starts a new short chain)
__device__ __forceinline__ void mma_set(float* c, const uint32_t* a,
                                        uint32_t b0, uint32_t b1) {
    asm volatile(
        "mma.sync.aligned.m16n8k16.row.col.f32.f16.f16.f32 "
        "{%0,%1,%2,%3},{%4,%5,%6,%7},{%8,%9},{%10,%11,%12,%13};"
        : "=f"(c[0]), "=f"(c[1]), "=f"(c[2]), "=f"(c[3])
        : "r"(a[0]), "r"(a[1]), "r"(a[2]), "r"(a[3]), "r"(b0), "r"(b1),
          "f"(0.f), "f"(0.f), "f"(0.f), "f"(0.f));
}
#define CP_ASYNC16(dst, src) \
    asm volatile("cp.async.cg.shared.global [%0], [%1], 16;" :: "r"(dst), "l"(src))
#define CP_COMMIT() asm volatile("cp.async.commit_group;" ::: "memory")
#define CP_WAIT1()  asm volatile("cp.async.wait_group 1;" ::: "memory")

// ---------------------------------------------------------------------------
// Edge kernels (no dense memset: only edge positions are ever touched)
// ---------------------------------------------------------------------------
__global__ void zero_edges_kernel(const int* __restrict__ oi, int E) {
    int e = blockIdx.x * blockDim.x + threadIdx.x;
    if (e < E) d_og[(size_t)oi[e] * NN + oi[E + e]] = 0.f;
}
__global__ void scatter_kernel(const int* __restrict__ oi,
                               const float* __restrict__ ow, int E) {
    int e = blockIdx.x * blockDim.x + threadIdx.x;
    if (e < E) atomicAdd(&d_og[(size_t)oi[e] * NN + oi[E + e]], ow[e]);
}

// ---------------------------------------------------------------------------
// Build split operands: y = 0.5*(x*w)/||x*w||; hi = fp16(y), lo = y - hi.
// Block scaling keeps every fp16 value in the NORMAL range:
// A = [hi*16 | hi/4 | lo*1024], B = [hi*16 | lo*1024 | hi/4]
// Every block-product has scale 2^8; epilogue de-scales by 2^-8 (exact).
// ---------------------------------------------------------------------------
__global__ void buildY_kernel(const float* __restrict__ x,
                              const float* __restrict__ wp) {
    int i = blockIdx.x;
    int d = threadIdx.x;   // 128 threads
    float xv = x[i * DD + d];
    __shared__ float sred[4];
#pragma unroll
    for (int p = 0; p < PP; p++) {
        float v = xv * wp[p * DD + d];
        float s = v * v;
#pragma unroll
        for (int o = 16; o > 0; o >>= 1) s += __shfl_xor_sync(0xffffffffu, s, o);
        if ((d & 31) == 0) sred[d >> 5] = s;
        __syncthreads();
        float tot = sred[0] + sred[1] + sred[2] + sred[3];
        float inv = 0.5f / fmaxf(sqrtf(tot), 1e-12f);
        float yv = v * inv;
        float hf = __half2float(__float2half_rn(yv));
        float lo = yv - hf;
        __half h16  = __float2half_rn(hf * 16.0f);      // exact scale
        __half hq   = __float2half_rn(hf * 0.25f);      // exact scale
        __half l1k  = __float2half_rn(lo * 1024.0f);
        size_t base = (size_t)i * KE;
        int k = p * DD + d;
        d_A[base + k]          = h16;
        d_A[base + KO + k]     = hq;
        d_A[base + 2 * KO + k] = l1k;
        d_B[base + k]          = h16;
        d_B[base + KO + k]     = l1k;
        d_B[base + 2 * KO + k] = hq;
        __syncthreads();
    }
}

// ---------------------------------------------------------------------------
// HMMA fp16 SYRK (K=1536), segmented accumulation, register-double-buffered
// ldmatrix fragments (hide LDSM latency under MMA issue), upper-tri tiles
// ---------------------------------------------------------------------------
#define STAGES 3
#define KSTEP 64
#define NSTEPS (KE / KSTEP)        // 24
#define SEG 2                      // k-steps per accumulation segment
#define TILE_BYTES 16384           // 128 rows x 128B
#define STAGE_BYTES (2 * TILE_BYTES)

__global__ __launch_bounds__(256, 1) void gemm_hmma_kernel(float* __restrict__ out) {
    int bi = blockIdx.y, bj = blockIdx.x;
    if (bj < bi) return;           // symmetric: upper-triangular tiles only

    extern __shared__ char dsm[];
    uint32_t smem = smem_u32(dsm);
    int tid = threadIdx.x, wid = tid >> 5, lane = tid & 31;
    int wr = wid >> 1, wc = wid & 1;   // warp tile: rows wr*32, cols wc*64

    const __half* Ag = d_A + (size_t)bi * 128 * KE;
    const __half* Bg = d_B + (size_t)bj * 128 * KE;

    // prefetch into stage ks%3 (always commits -> stable group count)
    auto prefetch = [&](int ks) {
        if (ks < NSTEPS) {
            uint32_t sa = smem + (ks % STAGES) * STAGE_BYTES;
            uint32_t sb = sa + TILE_BYTES;
            const __half* ga = Ag + ks * KSTEP;
            const __half* gb = Bg + ks * KSTEP;
#pragma unroll
            for (int l = 0; l < 4; l++) {
                int id = l * 256 + tid;        // 1024 16B-chunks per matrix
                int r = id >> 3, c = id & 7;
                uint32_t off = r * 128 + ((c ^ (r & 7)) << 4);  // SW128 swizzle
                CP_ASYNC16(sa + off, ga + (size_t)r * KE + c * 8);
                CP_ASYNC16(sb + off, gb + (size_t)r * KE + c * 8);
            }
        }
        CP_COMMIT();
    };

    float acc[2][8][4];    // tensor-unit working accumulator (short chains)
    float csum[2][8][4];   // RN-drained running sum
#pragma unroll
    for (int mt = 0; mt < 2; mt++)
#pragma unroll
        for (int nt = 0; nt < 8; nt++)
#pragma unroll
            for (int q = 0; q < 4; q++) csum[mt][nt][q] = 0.f;

    // per-lane ldmatrix address pieces
    int aRow = lane & 15;            // + wr*32 + mt*16
    int aHalf = lane >> 4;           // +0/+1 16B chunk
    int bRow = (lane & 7) + ((lane >> 4) << 3);
    int bHalf = (lane >> 3) & 1;

    // double-buffered fragments
    uint32_t af[2][2][4], bf[2][4][4];
    auto load_frags = [&](int buf, uint32_t sa, uint32_t sb, int k16) {
#pragma unroll
        for (int mt = 0; mt < 2; mt++) {
            int r = wr * 32 + mt * 16 + aRow;
            int c = 2 * k16 + aHalf;
            ldsm_x4(af[buf][mt], sa + r * 128 + ((c ^ (r & 7)) << 4));
        }
#pragma unroll
        for (int np = 0; np < 4; np++) {
            int r = wc * 64 + np * 16 + bRow;
            int c = 2 * k16 + bHalf;
            ldsm_x4(bf[buf][np], sb + r * 128 + ((c ^ (r & 7)) << 4));
        }
    };

    prefetch(0);
    prefetch(1);

    for (int ks = 0; ks < NSTEPS; ks++) {
        CP_WAIT1();
        __syncthreads();
        prefetch(ks + 2);

        uint32_t sa = smem + (ks % STAGES) * STAGE_BYTES;
        uint32_t sb = sa + TILE_BYTES;
        bool segStart = (ks % SEG) == 0;

        load_frags(0, sa, sb, 0);     // prime first fragment set
#pragma unroll
        for (int k16 = 0; k16 < 4; k16++) {
            int cur = k16 & 1;
            if (k16 < 3) load_frags(cur ^ 1, sa, sb, k16 + 1);  // hide LDSM latency
            if (segStart && k16 == 0) {
#pragma unroll
                for (int mt = 0; mt < 2; mt++)
#pragma unroll
                    for (int np = 0; np < 4; np++) {
                        mma_set(acc[mt][2 * np],     af[cur][mt], bf[cur][np][0], bf[cur][np][1]);
                        mma_set(acc[mt][2 * np + 1], af[cur][mt], bf[cur][np][2], bf[cur][np][3]);
                    }
            } else {
#pragma unroll
                for (int mt = 0; mt < 2; mt++)
#pragma unroll
                    for (int np = 0; np < 4; np++) {
                        mma_acc(acc[mt][2 * np],     af[cur][mt], bf[cur][np][0], bf[cur][np][1]);
                        mma_acc(acc[mt][2 * np + 1], af[cur][mt], bf[cur][np][2], bf[cur][np][3]);
                    }
            }
        }
        if ((ks % SEG) == SEG - 1) {   // drain segment with RN FADDs
#pragma unroll
            for (int mt = 0; mt < 2; mt++)
#pragma unroll
                for (int nt = 0; nt < 8; nt++)
#pragma unroll
                    for (int q = 0; q < 4; q++)
                        csum[mt][nt][q] += acc[mt][nt][q];
        }
    }

    // Epilogue: de-scale (2^-8), threshold, write row block; mirror lower tri
    int g = lane >> 2, tg = lane & 3;
#pragma unroll
    for (int mt = 0; mt < 2; mt++) {
#pragma unroll
        for (int h = 0; h < 2; h++) {
            int gi = bi * 128 + wr * 32 + mt * 16 + h * 8 + g;
            float* rowp = out + (size_t)gi * NN + bj * 128 + wc * 64 + tg * 2;
#pragma unroll
            for (int nt = 0; nt < 8; nt++) {
                float s0 = csum[mt][nt][2 * h] * OUT_DESCALE;
                float s1 = csum[mt][nt][2 * h + 1] * OUT_DESCALE;
                s0 = (s0 > EPS) ? s0 : 0.f;
                s1 = (s1 > EPS) ? s1 : 0.f;
                *(float2*)(rowp + nt * 8) = make_float2(s0, s1);
                if (bi != bj) {
                    int gj = bj * 128 + wc * 64 + nt * 8 + tg * 2;
                    out[(size_t)gj * NN + gi] = s0;
                    out[(size_t)(gj + 1) * NN + gi] = s1;
                }
            }
        }
    }
}

// ---------------------------------------------------------------------------
// Per-edge purification fixup (race-free, duplicate-idempotent)
// ---------------------------------------------------------------------------
__global__ void edge_fix_a(const int* __restrict__ oi,
                           const float* __restrict__ out, int E) {
    int e = blockIdx.x * blockDim.x + threadIdx.x;
    if (e >= E) return;
    int i = oi[e], j = oi[E + e];
    float og = d_og[(size_t)i * NN + j];
    float so = out[(size_t)i * NN + j];   // sim_g = sim if sim>eps else 0
    float s = so;
    if (so == 0.f) {
        // here sim <= eps, so sim*og > eps requires og > 1 (duplicate edges only)
        if (og > 1.0f) {
            const __half* ai = d_A + (size_t)i * KE;
            const __half* bj = d_B + (size_t)j * KE;
            float acc = 0.f;
#pragma unroll 4
            for (int k = 0; k < KO; k++) {
                float yi = __half2float(ai[k]) * 0.0625f +
                           __half2float(ai[2 * KO + k]) * 0.0009765625f;
                float yj = __half2float(bj[k]) * 0.0625f +
                           __half2float(bj[KO + k]) * 0.0009765625f;
                acc = fmaf(yi, yj, acc);
            }
            s = acc;
        } else {
            s = 0.f;
        }
    }
    d_val[e] = so + ((s * og > EPS) ? og : 0.f);
}
__global__ void edge_fix_b(const int* __restrict__ oi, float* __restrict__ out, int E) {
    int e = blockIdx.x * blockDim.x + threadIdx.x;
    if (e >= E) return;
    out[(size_t)oi[e] * NN + oi[E + e]] = d_val[e];
}

// ---------------------------------------------------------------------------
extern "C" void kernel_launch(void* const* d_in, const int* in_sizes, int n_in,
                              void* d_out, int out_size) {
    const float* x  = (const float*)d_in[0];
    const int*   oi = (const int*)d_in[1];
    const float* ow = (const float*)d_in[2];
    const float* wp = (const float*)d_in[3];
    float* out = (float*)d_out;
    int E = in_sizes[2];

    cudaFuncSetAttribute(gemm_hmma_kernel,
                         cudaFuncAttributeMaxDynamicSharedMemorySize,
                         STAGES * STAGE_BYTES);

    zero_edges_kernel<<<(E + 255) / 256, 256>>>(oi, E);
    scatter_kernel<<<(E + 255) / 256, 256>>>(oi, ow, E);
    buildY_kernel<<<NN, DD>>>(x, wp);
    dim3 grid(NN / 128, NN / 128);
    gemm_hmma_kernel<<<grid, 256, STAGES * STAGE_BYTES>>>(out);
    edge_fix_a<<<(E + 255) / 256, 256>>>(oi, out, E);
    edge_fix_b<<<(E + 255) / 256, 256>>>(oi, out, E);
}

// round 7
// speedup vs baseline: 1.0263x; 1.0263x over previous
#include <cuda_runtime.h>
#include <cuda_fp16.h>
#include <cstdint>

#define NN 8192
#define DD 128
#define PP 4
#define KO 512            // original concat feature dim
#define KE 1536           // split-3 extended K
#define EPS 0.3f
#define EMAX (1 << 19)
#define OUT_DESCALE 0.00390625f   // 2^-8 (exact)

// Scratch (allocation banned -> __device__ globals)
__device__ __half d_A[(size_t)NN * KE];   // 24 MB: [hi*2^4 | hi*2^-2 | lo*2^10]
__device__ __half d_B[(size_t)NN * KE];   // 24 MB: [hi*2^4 | lo*2^10 | hi*2^-2]
__device__ float  d_og[(size_t)NN * NN];  // only edge positions ever touched
__device__ float  d_val[EMAX];

// ---------------------------------------------------------------------------
__device__ __forceinline__ uint32_t smem_u32(const void* p) {
    uint32_t a;
    asm("{ .reg .u64 t; cvta.to.shared.u64 t, %1; cvt.u32.u64 %0, t; }" : "=r"(a) : "l"(p));
    return a;
}
__device__ __forceinline__ void ldsm_x4(uint32_t* r, uint32_t addr) {
    asm volatile("ldmatrix.sync.aligned.m8n8.x4.shared.b16 {%0,%1,%2,%3}, [%4];"
                 : "=r"(r[0]), "=r"(r[1]), "=r"(r[2]), "=r"(r[3]) : "r"(addr));
}
// chained accumulate: c = a*b + c  (tensor-unit add)
__device__ __forceinline__ void mma_acc(float* c, const uint32_t* a,
                                        uint32_t b0, uint32_t b1) {
    asm volatile(
        "mma.sync.aligned.m16n8k16.row.col.f32.f16.f16.f32 "
        "{%0,%1,%2,%3},{%4,%5,%6,%7},{%8,%9},{%0,%1,%2,%3};"
        : "+f"(c[0]), "+f"(c[1]), "+f"(c[2]), "+f"(c[3])
        : "r"(a[0]), "r"(a[1]), "r"(a[2]), "r"(a[3]), "r"(b0), "r"(b1));
}
// fresh-segment form: c = a*b + 0  (starts a new short chain)
__device__ __forceinline__ void mma_set(float* c, const uint32_t* a,
                                        uint32_t b0, uint32_t b1) {
    asm volatile(
        "mma.sync.aligned.m16n8k16.row.col.f32.f16.f16.f32 "
        "{%0,%1,%2,%3},{%4,%5,%6,%7},{%8,%9},{%10,%11,%12,%13};"
        : "=f"(c[0]), "=f"(c[1]), "=f"(c[2]), "=f"(c[3])
        : "r"(a[0]), "r"(a[1]), "r"(a[2]), "r"(a[3]), "r"(b0), "r"(b1),
          "f"(0.f), "f"(0.f), "f"(0.f), "f"(0.f));
}
#define CP_ASYNC16(dst, src) \
    asm volatile("cp.async.cg.shared.global [%0], [%1], 16;" :: "r"(dst), "l"(src))
#define CP_COMMIT() asm volatile("cp.async.commit_group;" ::: "memory")
#define CP_WAIT1()  asm volatile("cp.async.wait_group 1;" ::: "memory")

// ---------------------------------------------------------------------------
// Edge kernels (no dense memset: only edge positions are ever touched)
// ---------------------------------------------------------------------------
__global__ void zero_edges_kernel(const int* __restrict__ oi, int E) {
    int e = blockIdx.x * blockDim.x + threadIdx.x;
    if (e < E) d_og[(size_t)oi[e] * NN + oi[E + e]] = 0.f;
}
__global__ void scatter_kernel(const int* __restrict__ oi,
                               const float* __restrict__ ow, int E) {
    int e = blockIdx.x * blockDim.x + threadIdx.x;
    if (e < E) atomicAdd(&d_og[(size_t)oi[e] * NN + oi[E + e]], ow[e]);
}

// ---------------------------------------------------------------------------
// Build split operands: y = 0.5*(x*w)/||x*w||; hi = fp16(y), lo = y - hi.
// Block scaling keeps every fp16 value in the NORMAL range:
// A = [hi*16 | hi/4 | lo*1024], B = [hi*16 | lo*1024 | hi/4]
// Every block-product has scale 2^8; epilogue de-scales by 2^-8 (exact).
// ---------------------------------------------------------------------------
__global__ void buildY_kernel(const float* __restrict__ x,
                              const float* __restrict__ wp) {
    int i = blockIdx.x;
    int d = threadIdx.x;   // 128 threads
    float xv = x[i * DD + d];
    __shared__ float sred[4];
#pragma unroll
    for (int p = 0; p < PP; p++) {
        float v = xv * wp[p * DD + d];
        float s = v * v;
#pragma unroll
        for (int o = 16; o > 0; o >>= 1) s += __shfl_xor_sync(0xffffffffu, s, o);
        if ((d & 31) == 0) sred[d >> 5] = s;
        __syncthreads();
        float tot = sred[0] + sred[1] + sred[2] + sred[3];
        float inv = 0.5f / fmaxf(sqrtf(tot), 1e-12f);
        float yv = v * inv;
        float hf = __half2float(__float2half_rn(yv));
        float lo = yv - hf;
        __half h16  = __float2half_rn(hf * 16.0f);      // exact scale
        __half hq   = __float2half_rn(hf * 0.25f);      // exact scale
        __half l1k  = __float2half_rn(lo * 1024.0f);
        size_t base = (size_t)i * KE;
        int k = p * DD + d;
        d_A[base + k]          = h16;
        d_A[base + KO + k]     = hq;
        d_A[base + 2 * KO + k] = l1k;
        d_B[base + k]          = h16;
        d_B[base + KO + k]     = l1k;
        d_B[base + 2 * KO + k] = hq;
        __syncthreads();
    }
}

// ---------------------------------------------------------------------------
// HMMA fp16 SYRK (K=1536), 512 threads / 16 warps (4x4 grid, 32x32 warp
// tiles) for 4 warps/SMSP issue pressure; segmented accumulation; upper-tri
// ---------------------------------------------------------------------------
#define STAGES 3
#define KSTEP 64
#define NSTEPS (KE / KSTEP)        // 24
#define SEG 2                      // k-steps per accumulation segment
#define TILE_BYTES 16384           // 128 rows x 128B
#define STAGE_BYTES (2 * TILE_BYTES)
#define NTHREADS 512

__global__ __launch_bounds__(NTHREADS, 1) void gemm_hmma_kernel(float* __restrict__ out) {
    int bi = blockIdx.y, bj = blockIdx.x;
    if (bj < bi) return;           // symmetric: upper-triangular tiles only

    extern __shared__ char dsm[];
    uint32_t smem = smem_u32(dsm);
    int tid = threadIdx.x, wid = tid >> 5, lane = tid & 31;
    int wr = wid >> 2, wc = wid & 3;   // 4x4 warp grid: rows wr*32, cols wc*32

    const __half* Ag = d_A + (size_t)bi * 128 * KE;
    const __half* Bg = d_B + (size_t)bj * 128 * KE;

    // prefetch into stage ks%3 (always commits -> stable group count)
    auto prefetch = [&](int ks) {
        if (ks < NSTEPS) {
            uint32_t sa = smem + (ks % STAGES) * STAGE_BYTES;
            uint32_t sb = sa + TILE_BYTES;
            const __half* ga = Ag + ks * KSTEP;
            const __half* gb = Bg + ks * KSTEP;
#pragma unroll
            for (int l = 0; l < 2; l++) {
                int id = l * NTHREADS + tid;   // 1024 16B-chunks per matrix
                int r = id >> 3, c = id & 7;
                uint32_t off = r * 128 + ((c ^ (r & 7)) << 4);  // SW128 swizzle
                CP_ASYNC16(sa + off, ga + (size_t)r * KE + c * 8);
                CP_ASYNC16(sb + off, gb + (size_t)r * KE + c * 8);
            }
        }
        CP_COMMIT();
    };

    float acc[2][4][4];    // tensor-unit working accumulator (short chains)
    float csum[2][4][4];   // RN-drained running sum
#pragma unroll
    for (int mt = 0; mt < 2; mt++)
#pragma unroll
        for (int nt = 0; nt < 4; nt++)
#pragma unroll
            for (int q = 0; q < 4; q++) csum[mt][nt][q] = 0.f;

    // per-lane ldmatrix address pieces
    int aRow = lane & 15;            // + wr*32 + mt*16
    int aHalf = lane >> 4;           // +0/+1 16B chunk
    int bRow = (lane & 7) + ((lane >> 4) << 3);
    int bHalf = (lane >> 3) & 1;

    prefetch(0);
    prefetch(1);

    for (int ks = 0; ks < NSTEPS; ks++) {
        CP_WAIT1();
        __syncthreads();
        prefetch(ks + 2);

        uint32_t sa = smem + (ks % STAGES) * STAGE_BYTES;
        uint32_t sb = sa + TILE_BYTES;
        bool segStart = (ks % SEG) == 0;
#pragma unroll
        for (int k16 = 0; k16 < 4; k16++) {
            uint32_t a[2][4];
#pragma unroll
            for (int mt = 0; mt < 2; mt++) {
                int r = wr * 32 + mt * 16 + aRow;
                int c = 2 * k16 + aHalf;
                ldsm_x4(a[mt], sa + r * 128 + ((c ^ (r & 7)) << 4));
            }
            uint32_t b[2][4];
#pragma unroll
            for (int np = 0; np < 2; np++) {
                int r = wc * 32 + np * 16 + bRow;
                int c = 2 * k16 + bHalf;
                ldsm_x4(b[np], sb + r * 128 + ((c ^ (r & 7)) << 4));
            }
            if (segStart && k16 == 0) {
#pragma unroll
                for (int mt = 0; mt < 2; mt++)
#pragma unroll
                    for (int np = 0; np < 2; np++) {
                        mma_set(acc[mt][2 * np],     a[mt], b[np][0], b[np][1]);
                        mma_set(acc[mt][2 * np + 1], a[mt], b[np][2], b[np][3]);
                    }
            } else {
#pragma unroll
                for (int mt = 0; mt < 2; mt++)
#pragma unroll
                    for (int np = 0; np < 2; np++) {
                        mma_acc(acc[mt][2 * np],     a[mt], b[np][0], b[np][1]);
                        mma_acc(acc[mt][2 * np + 1], a[mt], b[np][2], b[np][3]);
                    }
            }
        }
        if ((ks % SEG) == SEG - 1) {   // drain segment with RN FADDs
#pragma unroll
            for (int mt = 0; mt < 2; mt++)
#pragma unroll
                for (int nt = 0; nt < 4; nt++)
#pragma unroll
                    for (int q = 0; q < 4; q++)
                        csum[mt][nt][q] += acc[mt][nt][q];
        }
    }

    // Epilogue: de-scale (2^-8), threshold, write row block; mirror lower tri
    int g = lane >> 2, tg = lane & 3;
#pragma unroll
    for (int mt = 0; mt < 2; mt++) {
#pragma unroll
        for (int h = 0; h < 2; h++) {
            int gi = bi * 128 + wr * 32 + mt * 16 + h * 8 + g;
            float* rowp = out + (size_t)gi * NN + bj * 128 + wc * 32 + tg * 2;
#pragma unroll
            for (int nt = 0; nt < 4; nt++) {
                float s0 = csum[mt][nt][2 * h] * OUT_DESCALE;
                float s1 = csum[mt][nt][2 * h + 1] * OUT_DESCALE;
                s0 = (s0 > EPS) ? s0 : 0.f;
                s1 = (s1 > EPS) ? s1 : 0.f;
                *(float2*)(rowp + nt * 8) = make_float2(s0, s1);
                if (bi != bj) {
                    int gj = bj * 128 + wc * 32 + nt * 8 + tg * 2;
                    out[(size_t)gj * NN + gi] = s0;
                    out[(size_t)(gj + 1) * NN + gi] = s1;
                }
            }
        }
    }
}

// ---------------------------------------------------------------------------
// Per-edge purification fixup (race-free, duplicate-idempotent)
// ---------------------------------------------------------------------------
__global__ void edge_fix_a(const int* __restrict__ oi,
                           const float* __restrict__ out, int E) {
    int e = blockIdx.x * blockDim.x + threadIdx.x;
    if (e >= E) return;
    int i = oi[e], j = oi[E + e];
    float og = d_og[(size_t)i * NN + j];
    float so = out[(size_t)i * NN + j];   // sim_g = sim if sim>eps else 0
    float s = so;
    if (so == 0.f) {
        // here sim <= eps, so sim*og > eps requires og > 1 (duplicate edges only)
        if (og > 1.0f) {
            const __half* ai = d_A + (size_t)i * KE;
            const __half* bj = d_B + (size_t)j * KE;
            float acc = 0.f;
#pragma unroll 4
            for (int k = 0; k < KO; k++) {
                float yi = __half2float(ai[k]) * 0.0625f +
                           __half2float(ai[2 * KO + k]) * 0.0009765625f;
                float yj = __half2float(bj[k]) * 0.0625f +
                           __half2float(bj[KO + k]) * 0.0009765625f;
                acc = fmaf(yi, yj, acc);
            }
            s = acc;
        } else {
            s = 0.f;
        }
    }
    d_val[e] = so + ((s * og > EPS) ? og : 0.f);
}
__global__ void edge_fix_b(const int* __restrict__ oi, float* __restrict__ out, int E) {
    int e = blockIdx.x * blockDim.x + threadIdx.x;
    if (e >= E) return;
    out[(size_t)oi[e] * NN + oi[E + e]] = d_val[e];
}

// ---------------------------------------------------------------------------
extern "C" void kernel_launch(void* const* d_in, const int* in_sizes, int n_in,
                              void* d_out, int out_size) {
    const float* x  = (const float*)d_in[0];
    const int*   oi = (const int*)d_in[1];
    const float* ow = (const float*)d_in[2];
    const float* wp = (const float*)d_in[3];
    float* out = (float*)d_out;
    int E = in_sizes[2];

    cudaFuncSetAttribute(gemm_hmma_kernel,
                         cudaFuncAttributeMaxDynamicSharedMemorySize,
                         STAGES * STAGE_BYTES);

    zero_edges_kernel<<<(E + 255) / 256, 256>>>(oi, E);
    scatter_kernel<<<(E + 255) / 256, 256>>>(oi, ow, E);
    buildY_kernel<<<NN, DD>>>(x, wp);
    dim3 grid(NN / 128, NN / 128);
    gemm_hmma_kernel<<<grid, NTHREADS, STAGES * STAGE_BYTES>>>(out);
    edge_fix_a<<<(E + 255) / 256, 256>>>(oi, out, E);
    edge_fix_b<<<(E + 255) / 256, 256>>>(oi, out, E);
}

// round 8
// speedup vs baseline: 1.2859x; 1.2530x over previous
#include <cuda_runtime.h>
#include <cuda_fp16.h>
#include <cstdint>

#define NN 8192
#define DD 128
#define PP 4
#define KK 512            // P*D concatenated feature dim
#define EPS 0.3f
#define EMAX (1 << 19)
#define CAND_MAX (1 << 20)
#define DESCALE 0.00390625f      // 2^-8 (each operand scaled by 16)

// Scratch (allocation banned -> __device__ globals)
__device__ __half d_H[(size_t)NN * KK];    //  8 MB: fp16(y)*16 (SYRK operand)
__device__ float  d_Yf[(size_t)NN * KK];   // 16 MB: fp32 y (exact recompute)
__device__ float  d_nh[NN], d_nl[NN];      // per-row norms for error margin
__device__ float  d_og[(size_t)NN * NN];   // only edge positions ever touched
__device__ float  d_val[EMAX];
__device__ int    d_ncand;
__device__ int2   d_cand[CAND_MAX];

// ---------------------------------------------------------------------------
__device__ __forceinline__ uint32_t smem_u32(const void* p) {
    uint32_t a;
    asm("{ .reg .u64 t; cvta.to.shared.u64 t, %1; cvt.u32.u64 %0, t; }" : "=r"(a) : "l"(p));
    return a;
}
__device__ __forceinline__ void ldsm_x4(uint32_t* r, uint32_t addr) {
    asm volatile("ldmatrix.sync.aligned.m8n8.x4.shared.b16 {%0,%1,%2,%3}, [%4];"
                 : "=r"(r[0]), "=r"(r[1]), "=r"(r[2]), "=r"(r[3]) : "r"(addr));
}
__device__ __forceinline__ void mma_acc(float* c, const uint32_t* a,
                                        uint32_t b0, uint32_t b1) {
    asm volatile(
        "mma.sync.aligned.m16n8k16.row.col.f32.f16.f16.f32 "
        "{%0,%1,%2,%3},{%4,%5,%6,%7},{%8,%9},{%0,%1,%2,%3};"
        : "+f"(c[0]), "+f"(c[1]), "+f"(c[2]), "+f"(c[3])
        : "r"(a[0]), "r"(a[1]), "r"(a[2]), "r"(a[3]), "r"(b0), "r"(b1));
}
__device__ __forceinline__ void mma_set(float* c, const uint32_t* a,
                                        uint32_t b0, uint32_t b1) {
    asm volatile(
        "mma.sync.aligned.m16n8k16.row.col.f32.f16.f16.f32 "
        "{%0,%1,%2,%3},{%4,%5,%6,%7},{%8,%9},{%10,%11,%12,%13};"
        : "=f"(c[0]), "=f"(c[1]), "=f"(c[2]), "=f"(c[3])
        : "r"(a[0]), "r"(a[1]), "r"(a[2]), "r"(a[3]), "r"(b0), "r"(b1),
          "f"(0.f), "f"(0.f), "f"(0.f), "f"(0.f));
}
#define CP_ASYNC16(dst, src) \
    asm volatile("cp.async.cg.shared.global [%0], [%1], 16;" :: "r"(dst), "l"(src))
#define CP_COMMIT() asm volatile("cp.async.commit_group;" ::: "memory")
#define CP_WAIT1()  asm volatile("cp.async.wait_group 1;" ::: "memory")

// ---------------------------------------------------------------------------
// Edge prep (no dense memset; also resets candidate counter)
// ---------------------------------------------------------------------------
__global__ void zero_edges_kernel(const int* __restrict__ oi, int E) {
    int e = blockIdx.x * blockDim.x + threadIdx.x;
    if (e == 0) d_ncand = 0;
    if (e < E) d_og[(size_t)oi[e] * NN + oi[E + e]] = 0.f;
}
__global__ void scatter_kernel(const int* __restrict__ oi,
                               const float* __restrict__ ow, int E) {
    int e = blockIdx.x * blockDim.x + threadIdx.x;
    if (e < E) atomicAdd(&d_og[(size_t)oi[e] * NN + oi[E + e]], ow[e]);
}

// ---------------------------------------------------------------------------
// Build: y = 0.5*(x*w)/||x*w||; H = fp16(y)*16 (exact pow2 scale);
// Yf = fp32 y; per-row norms nh = ||fp16(y)||, nl = ||y - fp16(y)|| + flush
// term (elements whose scaled hi is fp16-subnormal count fully toward nl).
// ---------------------------------------------------------------------------
__global__ void buildY_kernel(const float* __restrict__ x,
                              const float* __restrict__ wp) {
    int i = blockIdx.x;
    int d = threadIdx.x;   // 128 threads
    float xv = x[i * DD + d];
    __shared__ float sred[4], hred[4], lred[4];
    float hi2 = 0.f, lo2 = 0.f;
#pragma unroll
    for (int p = 0; p < PP; p++) {
        float v = xv * wp[p * DD + d];
        float s = v * v;
#pragma unroll
        for (int o = 16; o > 0; o >>= 1) s += __shfl_xor_sync(0xffffffffu, s, o);
        if ((d & 31) == 0) sred[d >> 5] = s;
        __syncthreads();
        float tot = sred[0] + sred[1] + sred[2] + sred[3];
        float inv = 0.5f / fmaxf(sqrtf(tot), 1e-12f);
        float yv = v * inv;
        float hf = __half2float(__float2half_rn(yv));
        float lo = yv - hf;
        // flush hazard: scaled hi below fp16 min-normal gets flushed in HMMA
        float e = fabsf(lo) + ((fabsf(hf) < 3.815e-6f) ? fabsf(hf) : 0.f);
        int k = p * DD + d;
        d_H[(size_t)i * KK + k]  = __float2half_rn(hf * 16.0f);  // exact
        d_Yf[(size_t)i * KK + k] = yv;
        hi2 += hf * hf;
        lo2 += e * e;
        __syncthreads();
    }
#pragma unroll
    for (int o = 16; o > 0; o >>= 1) {
        hi2 += __shfl_xor_sync(0xffffffffu, hi2, o);
        lo2 += __shfl_xor_sync(0xffffffffu, lo2, o);
    }
    if ((d & 31) == 0) { hred[d >> 5] = hi2; lred[d >> 5] = lo2; }
    __syncthreads();
    if (d == 0) {
        d_nh[i] = sqrtf(hred[0] + hred[1] + hred[2] + hred[3]);
        d_nl[i] = sqrtf(lred[0] + lred[1] + lred[2] + lred[3]);
    }
}

// ---------------------------------------------------------------------------
// HMMA fp16 SYRK (K=512, hi-only), segmented accumulation, margin-based
// candidate detection, thresholded epilogue + mirror; triangular 1-D grid
// ---------------------------------------------------------------------------
#define STAGES 3
#define KSTEP 64
#define NSTEPS (KK / KSTEP)        // 8
#define SEG 2
#define TILE_BYTES 16384           // 128 rows x 128B
#define STAGE_BYTES (2 * TILE_BYTES)
#define NTHREADS 512
#define NBLK (NN / 128)            // 64
#define NTRI (NBLK * (NBLK + 1) / 2)   // 2080

__global__ __launch_bounds__(NTHREADS, 1) void gemm_hmma_kernel(float* __restrict__ out) {
    // triangular index -> (bi, bj), bj >= bi
    int t = blockIdx.x;
    int r = (int)floorf((2.f * NBLK + 1.f -
                         sqrtf((2.f * NBLK + 1.f) * (2.f * NBLK + 1.f) - 8.f * t)) * 0.5f);
    #define TSTART(rr) ((rr) * NBLK - ((rr) * ((rr) - 1)) / 2)
    while (TSTART(r + 1) <= t) ++r;
    while (TSTART(r) > t) --r;
    int bi = r, bj = r + (t - TSTART(r));

    extern __shared__ char dsm[];
    uint32_t smem = smem_u32(dsm);
    int tid = threadIdx.x, wid = tid >> 5, lane = tid & 31;
    int wr = wid >> 2, wc = wid & 3;   // 4x4 warp grid: 32x32 warp tiles

    const __half* Ag = d_H + (size_t)bi * 128 * KK;
    const __half* Bg = d_H + (size_t)bj * 128 * KK;

    auto prefetch = [&](int ks) {
        if (ks < NSTEPS) {
            uint32_t sa = smem + (ks % STAGES) * STAGE_BYTES;
            uint32_t sb = sa + TILE_BYTES;
            const __half* ga = Ag + ks * KSTEP;
            const __half* gb = Bg + ks * KSTEP;
#pragma unroll
            for (int l = 0; l < 2; l++) {
                int id = l * NTHREADS + tid;   // 1024 16B-chunks per matrix
                int rr = id >> 3, c = id & 7;
                uint32_t off = rr * 128 + ((c ^ (rr & 7)) << 4);  // SW128 swizzle
                CP_ASYNC16(sa + off, ga + (size_t)rr * KK + c * 8);
                CP_ASYNC16(sb + off, gb + (size_t)rr * KK + c * 8);
            }
        }
        CP_COMMIT();
    };

    float acc[2][4][4];
    float csum[2][4][4];
#pragma unroll
    for (int mt = 0; mt < 2; mt++)
#pragma unroll
        for (int nt = 0; nt < 4; nt++)
#pragma unroll
            for (int q = 0; q < 4; q++) csum[mt][nt][q] = 0.f;

    int aRow = lane & 15;
    int aHalf = lane >> 4;
    int bRow = (lane & 7) + ((lane >> 4) << 3);
    int bHalf = (lane >> 3) & 1;

    prefetch(0);
    prefetch(1);

    for (int ks = 0; ks < NSTEPS; ks++) {
        CP_WAIT1();
        __syncthreads();
        prefetch(ks + 2);

        uint32_t sa = smem + (ks % STAGES) * STAGE_BYTES;
        uint32_t sb = sa + TILE_BYTES;
        bool segStart = (ks % SEG) == 0;
#pragma unroll
        for (int k16 = 0; k16 < 4; k16++) {
            uint32_t a[2][4];
#pragma unroll
            for (int mt = 0; mt < 2; mt++) {
                int rr = wr * 32 + mt * 16 + aRow;
                int c = 2 * k16 + aHalf;
                ldsm_x4(a[mt], sa + rr * 128 + ((c ^ (rr & 7)) << 4));
            }
            uint32_t b[2][4];
#pragma unroll
            for (int np = 0; np < 2; np++) {
                int rr = wc * 32 + np * 16 + bRow;
                int c = 2 * k16 + bHalf;
                ldsm_x4(b[np], sb + rr * 128 + ((c ^ (rr & 7)) << 4));
            }
            if (segStart && k16 == 0) {
#pragma unroll
                for (int mt = 0; mt < 2; mt++)
#pragma unroll
                    for (int np = 0; np < 2; np++) {
                        mma_set(acc[mt][2 * np],     a[mt], b[np][0], b[np][1]);
                        mma_set(acc[mt][2 * np + 1], a[mt], b[np][2], b[np][3]);
                    }
            } else {
#pragma unroll
                for (int mt = 0; mt < 2; mt++)
#pragma unroll
                    for (int np = 0; np < 2; np++) {
                        mma_acc(acc[mt][2 * np],     a[mt], b[np][0], b[np][1]);
                        mma_acc(acc[mt][2 * np + 1], a[mt], b[np][2], b[np][3]);
                    }
            }
        }
        if ((ks % SEG) == SEG - 1) {   // RN drain
#pragma unroll
            for (int mt = 0; mt < 2; mt++)
#pragma unroll
                for (int nt = 0; nt < 4; nt++)
#pragma unroll
                    for (int q = 0; q < 4; q++)
                        csum[mt][nt][q] += acc[mt][nt][q];
        }
    }

    // Epilogue: de-scale, margin-check, threshold, write + mirror
    int g = lane >> 2, tg = lane & 3;
    float nhj[4][2], nlj[4][2];
#pragma unroll
    for (int nt = 0; nt < 4; nt++)
#pragma unroll
        for (int q2 = 0; q2 < 2; q2++) {
            int gj = bj * 128 + wc * 32 + nt * 8 + tg * 2 + q2;
            nhj[nt][q2] = d_nh[gj];
            nlj[nt][q2] = d_nl[gj];
        }
#pragma unroll
    for (int mt = 0; mt < 2; mt++) {
#pragma unroll
        for (int h = 0; h < 2; h++) {
            int gi = bi * 128 + wr * 32 + mt * 16 + h * 8 + g;
            float nhi = d_nh[gi], nli = d_nl[gi];
            float* rowp = out + (size_t)gi * NN + bj * 128 + wc * 32 + tg * 2;
#pragma unroll
            for (int nt = 0; nt < 4; nt++) {
                float s0 = csum[mt][nt][2 * h] * DESCALE;
                float s1 = csum[mt][nt][2 * h + 1] * DESCALE;
                int gj0 = bj * 128 + wc * 32 + nt * 8 + tg * 2;
                float m0 = nhi * nlj[nt][0] + nli * nhj[nt][0] + 4e-6f;
                float m1 = nhi * nlj[nt][1] + nli * nhj[nt][1] + 4e-6f;
                if (fabsf(s0 - EPS) < m0) {
                    int idx = atomicAdd(&d_ncand, 1);
                    if (idx < CAND_MAX) d_cand[idx] = make_int2(gi, gj0);
                }
                if (fabsf(s1 - EPS) < m1) {
                    int idx = atomicAdd(&d_ncand, 1);
                    if (idx < CAND_MAX) d_cand[idx] = make_int2(gi, gj0 + 1);
                }
                s0 = (s0 > EPS) ? s0 : 0.f;
                s1 = (s1 > EPS) ? s1 : 0.f;
                *(float2*)(rowp + nt * 8) = make_float2(s0, s1);
                if (bi != bj) {
                    out[(size_t)gj0 * NN + gi] = s0;
                    out[(size_t)(gj0 + 1) * NN + gi] = s1;
                }
            }
        }
    }
}

// ---------------------------------------------------------------------------
// Exact (fp64) recompute of margin candidates; patches entry + mirror
// ---------------------------------------------------------------------------
__global__ void patch_kernel(float* __restrict__ out) {
    int nc = d_ncand;
    if (nc > CAND_MAX) nc = CAND_MAX;
    int gw = (blockIdx.x * blockDim.x + threadIdx.x) >> 5;
    int lane = threadIdx.x & 31;
    int nw = (gridDim.x * blockDim.x) >> 5;
    for (int c = gw; c < nc; c += nw) {
        int2 e = d_cand[c];
        const float* yi = d_Yf + (size_t)e.x * KK;
        const float* yj = d_Yf + (size_t)e.y * KK;
        double a = 0.0;
        for (int k = lane; k < KK; k += 32) a += (double)yi[k] * (double)yj[k];
#pragma unroll
        for (int o = 16; o > 0; o >>= 1) a += __shfl_xor_sync(0xffffffffu, a, o);
        if (lane == 0) {
            float s = (float)a;
            float sg = (s > EPS) ? s : 0.f;
            out[(size_t)e.x * NN + e.y] = sg;
            out[(size_t)e.y * NN + e.x] = sg;
        }
    }
}

// ---------------------------------------------------------------------------
// Per-edge purification fixup (race-free, duplicate-idempotent)
// ---------------------------------------------------------------------------
__global__ void edge_fix_a(const int* __restrict__ oi,
                           const float* __restrict__ out, int E) {
    int e = blockIdx.x * blockDim.x + threadIdx.x;
    if (e >= E) return;
    int i = oi[e], j = oi[E + e];
    float og = d_og[(size_t)i * NN + j];
    float so = out[(size_t)i * NN + j];   // sim_g (patched -> decisions exact)
    float purif = 0.f;
    bool need_exact;
    if (so == 0.f) {
        // s <= eps certain; s*og > eps possible only when og > 1 (duplicates)
        need_exact = (og > 1.0f);
    } else {
        float m = d_nh[i] * d_nl[j] + d_nl[i] * d_nh[j] + 4e-6f;
        need_exact = fabsf(so * og - EPS) < m * og + 1e-6f;
        if (!need_exact) purif = (so * og > EPS) ? og : 0.f;
    }
    if (need_exact) {
        const float* yi = d_Yf + (size_t)i * KK;
        const float* yj = d_Yf + (size_t)j * KK;
        double a = 0.0;
        for (int k = 0; k < KK; k++) a += (double)yi[k] * (double)yj[k];
        float s = (float)a;
        purif = (s * og > EPS) ? og : 0.f;
    }
    d_val[e] = so + purif;
}
__global__ void edge_fix_b(const int* __restrict__ oi, float* __restrict__ out, int E) {
    int e = blockIdx.x * blockDim.x + threadIdx.x;
    if (e >= E) return;
    out[(size_t)oi[e] * NN + oi[E + e]] = d_val[e];
}

// ---------------------------------------------------------------------------
extern "C" void kernel_launch(void* const* d_in, const int* in_sizes, int n_in,
                              void* d_out, int out_size) {
    const float* x  = (const float*)d_in[0];
    const int*   oi = (const int*)d_in[1];
    const float* ow = (const float*)d_in[2];
    const float* wp = (const float*)d_in[3];
    float* out = (float*)d_out;
    int E = in_sizes[2];

    cudaFuncSetAttribute(gemm_hmma_kernel,
                         cudaFuncAttributeMaxDynamicSharedMemorySize,
                         STAGES * STAGE_BYTES);

    zero_edges_kernel<<<(E + 255) / 256, 256>>>(oi, E);
    scatter_kernel<<<(E + 255) / 256, 256>>>(oi, ow, E);
    buildY_kernel<<<NN, DD>>>(x, wp);
    gemm_hmma_kernel<<<NTRI, NTHREADS, STAGES * STAGE_BYTES>>>(out);
    patch_kernel<<<256, 256>>>(out);
    edge_fix_a<<<(E + 255) / 256, 256>>>(oi, out, E);
    edge_fix_b<<<(E + 255) / 256, 256>>>(oi, out, E);
}